// round 14
// baseline (speedup 1.0000x reference)
#include <cuda_runtime.h>
#include <math.h>

// Row-normalize: out[r, :] = in[r, :] * inv(sum(in[r, :])), inv->0 if non-finite.
// Row length fixed at 1024 f32 = 256 float4.
// R13: TWO warps per row, 4 float4 per lane (was 8). Halves the live data
// registers (47 -> ~32), lifting occupancy 49% -> ~70% to push DRAM% higher.
// Cross-warp row sum via a 2-element smem exchange per row.

#define ROW_LEN 1024
#define VEC_PER_ROW (ROW_LEN / 4)   // 256 float4
#define VEC_PER_LANE 4              // 4 float4 per lane, 2 warps x 32 lanes x 4 = 256
#define WARPS_PER_BLOCK 8           // 4 rows per block
#define ROWS_PER_BLOCK (WARPS_PER_BLOCK / 2)
#define THREADS_PER_BLOCK (WARPS_PER_BLOCK * 32)

__global__ __launch_bounds__(THREADS_PER_BLOCK)
void normalizer_kernel(const float4* __restrict__ in,
                       float4* __restrict__ out,
                       int n_rows)
{
    __shared__ float part[WARPS_PER_BLOCK];

    const int warp_id = threadIdx.x >> 5;
    const int lane    = threadIdx.x & 31;
    const int row     = blockIdx.x * ROWS_PER_BLOCK + (warp_id >> 1);
    const int half    = warp_id & 1;            // which half of the row
    const bool active = (row < n_rows);

    const size_t base = (size_t)row * VEC_PER_ROW + half * (VEC_PER_ROW / 2);
    const float4* row_in  = in  + base;
    float4*       row_out = out + base;

    // Front-batched streaming loads: 4 independent LDG.128 per lane.
    float4 v[VEC_PER_LANE];
    if (active) {
#pragma unroll
        for (int k = 0; k < VEC_PER_LANE; k++) {
            v[k] = __ldcs(&row_in[lane + k * 32]);
        }
    } else {
#pragma unroll
        for (int k = 0; k < VEC_PER_LANE; k++) {
            v[k] = make_float4(0.f, 0.f, 0.f, 0.f);
        }
    }

    // Per-lane partial sum, then warp butterfly reduction.
    float s = 0.0f;
#pragma unroll
    for (int k = 0; k < VEC_PER_LANE; k++) {
        s += (v[k].x + v[k].y) + (v[k].z + v[k].w);
    }
#pragma unroll
    for (int off = 16; off > 0; off >>= 1) {
        s += __shfl_xor_sync(0xFFFFFFFFu, s, off);
    }

    // Exchange half-row sums between the warp pair via smem.
    if (lane == 0) part[warp_id] = s;
    __syncthreads();
    const float total = part[warp_id & ~1] + part[warp_id | 1];

    float inv = 1.0f / total;
    if (!isfinite(inv)) inv = 0.0f;

    // Scale from registers and store (streaming).
    if (active) {
#pragma unroll
        for (int k = 0; k < VEC_PER_LANE; k++) {
            float4 o;
            o.x = v[k].x * inv;
            o.y = v[k].y * inv;
            o.z = v[k].z * inv;
            o.w = v[k].w * inv;
            __stcs(&row_out[lane + k * 32], o);
        }
    }
}

extern "C" void kernel_launch(void* const* d_in, const int* in_sizes, int n_in,
                              void* d_out, int out_size)
{
    const float4* in  = (const float4*)d_in[0];
    float4*       out = (float4*)d_out;

    const int total  = in_sizes[0];          // 2*32*1024*1024 = 67108864
    const int n_rows = total / ROW_LEN;      // 65536

    const int blocks = (n_rows + ROWS_PER_BLOCK - 1) / ROWS_PER_BLOCK; // 16384
    normalizer_kernel<<<blocks, THREADS_PER_BLOCK>>>(in, out, n_rows);
}

// round 15
// speedup vs baseline: 1.0004x; 1.0004x over previous
#include <cuda_runtime.h>
#include <math.h>

// Row-normalize: out[r, :] = in[r, :] * inv(sum(in[r, :])), inv->0 if non-finite.
// Row = 1024 f32 = 128 x 32B (v8) chunks. One warp per row; each lane owns
// 4 x 256-bit (v8.f32) loads/stores (sm_103a 256-bit global access).
// R15: 256-bit requests — halve request count into LSU/LTS, denser DRAM bursts.

#define ROW_LEN 1024
#define V8_PER_ROW (ROW_LEN / 8)    // 128 v8 chunks
#define V8_PER_LANE 4               // 32 lanes * 4 = 128
#define WARPS_PER_BLOCK 8
#define THREADS_PER_BLOCK (WARPS_PER_BLOCK * 32)

__device__ __forceinline__ void ldg_v8(const float* p, float* r) {
    asm volatile("ld.global.v8.f32 {%0,%1,%2,%3,%4,%5,%6,%7}, [%8];"
                 : "=f"(r[0]), "=f"(r[1]), "=f"(r[2]), "=f"(r[3]),
                   "=f"(r[4]), "=f"(r[5]), "=f"(r[6]), "=f"(r[7])
                 : "l"(p));
}

__device__ __forceinline__ void stg_v8(float* p, const float* r) {
    asm volatile("st.global.v8.f32 [%0], {%1,%2,%3,%4,%5,%6,%7,%8};"
                 :: "l"(p),
                    "f"(r[0]), "f"(r[1]), "f"(r[2]), "f"(r[3]),
                    "f"(r[4]), "f"(r[5]), "f"(r[6]), "f"(r[7])
                 : "memory");
}

__global__ __launch_bounds__(THREADS_PER_BLOCK)
void normalizer_kernel(const float* __restrict__ in,
                       float* __restrict__ out,
                       int n_rows)
{
    const int warp_id = threadIdx.x >> 5;
    const int lane    = threadIdx.x & 31;
    const int row     = blockIdx.x * WARPS_PER_BLOCK + warp_id;
    if (row >= n_rows) return;

    const float* row_in  = in  + (size_t)row * ROW_LEN;
    float*       row_out = out + (size_t)row * ROW_LEN;

    // Front-batched 256-bit loads: 4 independent LDG.256 per lane (MLP=4, 128B in flight/lane).
    float v[V8_PER_LANE][8];
#pragma unroll
    for (int k = 0; k < V8_PER_LANE; k++) {
        ldg_v8(row_in + (size_t)(lane + k * 32) * 8, v[k]);
    }

    // Per-lane partial sum.
    float s = 0.0f;
#pragma unroll
    for (int k = 0; k < V8_PER_LANE; k++) {
        float t0 = (v[k][0] + v[k][1]) + (v[k][2] + v[k][3]);
        float t1 = (v[k][4] + v[k][5]) + (v[k][6] + v[k][7]);
        s += t0 + t1;
    }

    // Warp butterfly reduction -> all lanes hold the full row sum.
#pragma unroll
    for (int off = 16; off > 0; off >>= 1) {
        s += __shfl_xor_sync(0xFFFFFFFFu, s, off);
    }

    float inv = 1.0f / s;
    if (!isfinite(inv)) inv = 0.0f;

    // Scale in registers, 256-bit stores.
#pragma unroll
    for (int k = 0; k < V8_PER_LANE; k++) {
        float o[8];
#pragma unroll
        for (int j = 0; j < 8; j++) o[j] = v[k][j] * inv;
        stg_v8(row_out + (size_t)(lane + k * 32) * 8, o);
    }
}

extern "C" void kernel_launch(void* const* d_in, const int* in_sizes, int n_in,
                              void* d_out, int out_size)
{
    const float* in  = (const float*)d_in[0];
    float*       out = (float*)d_out;

    const int total  = in_sizes[0];          // 2*32*1024*1024 = 67108864
    const int n_rows = total / ROW_LEN;      // 65536

    const int blocks = (n_rows + WARPS_PER_BLOCK - 1) / WARPS_PER_BLOCK; // 8192
    normalizer_kernel<<<blocks, THREADS_PER_BLOCK>>>(in, out, n_rows);
}